// round 13
// baseline (speedup 1.0000x reference)
#include <cuda_runtime.h>
#include <cuda_fp16.h>
#include <cstdint>

#define C    128
#define NTH  256
#define HW   16384

#define WSZ 360448u    // 11 chunks * 32768B fp16-hi fragment images
__device__ __align__(16) unsigned char g_wfrag[WSZ];

// ---- smem layout (bytes) ----
#define OFF_X    0                      // fp32 X, skewed layout, ~35KB
#define OFF_BA   35072                  // act tile (y1/y2) / k0 buf
#define OFF_BW   (OFF_BA + 16384)       // wht tile, later k3 buf
#define OFF_BK   (OFF_BW + 16384)       // k1 buf
#define OFF_K2   (OFF_BK + 16384)       // k2 buf (was RS; r lives in regs now)
#define SMEM_TOT (OFF_K2 + 16384)       // 100608

// X row index: stride 68 floats + 16B skew per 8 rows (bank-spread for LN mapping)
__device__ __forceinline__ int XI(int c) { return c * 68 + ((c >> 3) << 2); }

// ---- helpers ----
__device__ __forceinline__ uint32_t pack_h(float lo, float hi) {
    uint32_t d;
    asm("cvt.rn.f16x2.f32 %0, %1, %2;" : "=r"(d) : "f"(hi), "f"(lo));
    return d;
}
__device__ __forceinline__ float2 unpack_h(uint32_t v) {
    __half2 h = *reinterpret_cast<__half2*>(&v);
    return __half22float2(h);
}
__device__ __forceinline__ float sigm(float v) { return 1.0f / (1.0f + __expf(-v)); }

__device__ __forceinline__ void ldsm4t(uint32_t& r0, uint32_t& r1, uint32_t& r2,
                                       uint32_t& r3, uint32_t addr) {
    asm volatile("ldmatrix.sync.aligned.m8n8.x4.trans.shared.b16 {%0,%1,%2,%3}, [%4];"
                 : "=r"(r0), "=r"(r1), "=r"(r2), "=r"(r3) : "r"(addr));
}
__device__ __forceinline__ void mma16(float* d, const uint4& a, uint32_t b0, uint32_t b1) {
    asm volatile("mma.sync.aligned.m16n8k16.row.col.f32.f16.f16.f32 "
                 "{%0,%1,%2,%3}, {%4,%5,%6,%7}, {%8,%9}, {%0,%1,%2,%3};"
                 : "+f"(d[0]), "+f"(d[1]), "+f"(d[2]), "+f"(d[3])
                 : "r"(a.x), "r"(a.y), "r"(a.z), "r"(a.w), "r"(b0), "r"(b1));
}
__device__ __forceinline__ void zero8(float (*a)[4]) {
    #pragma unroll
    for (int i = 0; i < 8; i++)
        #pragma unroll
        for (int j = 0; j < 4; j++) a[i][j] = 0.f;
}
// sum across the 16 channel-parts of one token group (16-lane segment)
__device__ __forceinline__ float4 red16(float4 v) {
    #pragma unroll
    for (int m = 1; m <= 8; m <<= 1) {
        v.x += __shfl_xor_sync(0xffffffffu, v.x, m, 16);
        v.y += __shfl_xor_sync(0xffffffffu, v.y, m, 16);
        v.z += __shfl_xor_sync(0xffffffffu, v.z, m, 16);
        v.w += __shfl_xor_sync(0xffffffffu, v.w, m, 16);
    }
    return v;
}

// common per-lane B addressing
struct BAddr {
    int kadd;
    uint32_t coff[4];
};
__device__ __forceinline__ BAddr baddr(int lane) {
    BAddr r;
    const int grp  = lane >> 3, r8 = lane & 7;
    r.kadd = (grp & 1) * 8 + r8;
    const int cgrp = grp >> 1;
    #pragma unroll
    for (int ntp = 0; ntp < 4; ntp++)
        r.coff[ntp] = (uint32_t)(((ntp * 2 + cgrp) ^ r8) << 4);
    return r;
}

// gemm: D[16 out x 64 tok] per warp; single weight term; R10/R12 schedule (unroll 2).
__device__ __forceinline__ void gemm16(float (*acc)[4],
    const unsigned char* __restrict__ wfh, uint32_t bh, int lane)
{
    BAddr ad = baddr(lane);
    #pragma unroll 2
    for (int kt = 0; kt < 8; kt++) {
        uint4 A = *reinterpret_cast<const uint4*>(wfh + kt * 4096);
        uint32_t rowb = bh + (uint32_t)((kt * 16 + ad.kadd) * 128);
        uint32_t b[16];
        #pragma unroll
        for (int ntp = 0; ntp < 4; ntp++)
            ldsm4t(b[4*ntp], b[4*ntp+1], b[4*ntp+2], b[4*ntp+3], rowb + ad.coff[ntp]);
        #pragma unroll
        for (int ntp = 0; ntp < 4; ntp++) {
            mma16(acc[2*ntp],   A, b[4*ntp],   b[4*ntp+1]);
            mma16(acc[2*ntp+1], A, b[4*ntp+2], b[4*ntp+3]);
        }
    }
}

// fused gemm: two weight chunks against ONE B-tile read (halves LDSM for the pair).
// unroll 1: keeps live registers (2 acc sets) under the RF cap — R11 lesson.
__device__ __forceinline__ void gemm16x2(float (*accA)[4], float (*accB)[4],
    const unsigned char* __restrict__ wfA, const unsigned char* __restrict__ wfB,
    uint32_t bh, int lane)
{
    BAddr ad = baddr(lane);
    #pragma unroll 1
    for (int kt = 0; kt < 8; kt++) {
        uint4 A0 = *reinterpret_cast<const uint4*>(wfA + kt * 4096);
        uint4 A1 = *reinterpret_cast<const uint4*>(wfB + kt * 4096);
        uint32_t rowb = bh + (uint32_t)((kt * 16 + ad.kadd) * 128);
        uint32_t b[16];
        #pragma unroll
        for (int ntp = 0; ntp < 4; ntp++)
            ldsm4t(b[4*ntp], b[4*ntp+1], b[4*ntp+2], b[4*ntp+3], rowb + ad.coff[ntp]);
        #pragma unroll
        for (int ntp = 0; ntp < 4; ntp++) {
            mma16(accA[2*ntp],   A0, b[4*ntp],   b[4*ntp+1]);
            mma16(accA[2*ntp+1], A0, b[4*ntp+2], b[4*ntp+3]);
        }
        #pragma unroll
        for (int ntp = 0; ntp < 4; ntp++) {
            mma16(accB[2*ntp],   A1, b[4*ntp],   b[4*ntp+1]);
            mma16(accB[2*ntp+1], A1, b[4*ntp+2], b[4*ntp+3]);
        }
    }
}

// ---- prep: fp32 weights -> fragment-ordered fp16 hi images ----
// chunk q: 0=Wout 1=Wwhiten 2=Wrecep 3..6=Wkey rows ch*128.. 7..10=Wvalue cols ch*128..
__global__ void __launch_bounds__(NTH) prep_kernel(
    const float* __restrict__ Wout, const float* __restrict__ Wwh,
    const float* __restrict__ Wkey, const float* __restrict__ Wrec,
    const float* __restrict__ Wval)
{
    int e = blockIdx.x * NTH + threadIdx.x;
    if (e >= 11 * 64 * 32) return;
    int lane = e & 31, mt = (e >> 5) & 7, kt = (e >> 8) & 7, q = e >> 11;
    int r  = lane >> 2;
    int cb = (lane & 3) * 2;
    float v[8];
    #pragma unroll
    for (int j = 0; j < 8; j++) {
        int row = mt * 16 + r + ((j >> 1) & 1) * 8;
        int col = kt * 16 + cb + (j >> 2) * 8 + (j & 1);
        float w;
        if (q == 0)      w = Wout[row * 128 + col];
        else if (q == 1) w = Wwh[row * 128 + col];
        else if (q == 2) w = Wrec[row * 128 + col];
        else if (q <= 6) w = Wkey[((q - 3) * 128 + row) * 128 + col];
        else             w = Wval[row * 512 + (q - 7) * 128 + col];
        v[j] = w;
    }
    uint4 hi;
    uint32_t* hp = &hi.x;
    #pragma unroll
    for (int p = 0; p < 4; p++)
        hp[p] = pack_h(v[2*p], v[2*p+1]);
    size_t off = (size_t)(((q * 8 + kt) * 8 + mt) * 32 + lane) * 16;
    *reinterpret_cast<uint4*>(g_wfrag + off) = hi;
}

// ---- main ----
__global__ void __launch_bounds__(NTH, 2) rwkv_mma_kernel(
    const float* __restrict__ x,
    const float* __restrict__ ln0_g, const float* __restrict__ ln0_b,
    const float* __restrict__ ln1_g, const float* __restrict__ ln1_b,
    const float* __restrict__ ln2_g, const float* __restrict__ ln2_b,
    float* __restrict__ out)
{
    extern __shared__ char sm[];
    const int tid  = threadIdx.x;
    const int wid  = tid >> 5;
    const int lane = tid & 31;
    const uint32_t smb = (uint32_t)__cvta_generic_to_shared(sm);

    const int tile = blockIdx.x;
    const int b    = tile >> 8;
    const int hw0  = (tile & 255) * 64;
    const float* xb = x   + (size_t)b * C * HW + hw0;
    float*       ob = out + (size_t)b * C * HW + hw0;

    float* X = (float*)(sm + OFF_X);

    // load X tile (float4 over tokens, 16 threads per channel row)
    #pragma unroll
    for (int k = 0; k < 8; k++) {
        int idx = tid + k * NTH;
        int c = idx >> 4, t = (idx & 15) * 4;
        *reinterpret_cast<float4*>(&X[XI(c) + t]) =
            *reinterpret_cast<const float4*>(&xb[c * HW + t]);
    }
    __syncthreads();

    // LN mapping: thread = tg*16 + part; part owns 8 channels, tg owns 4 tokens.
    const int part = tid & 15;
    const int tg   = tid >> 4;
    const int lt0  = tg * 4;

    auto bstore = [&](int off, int c, float o0, float o1, float o2, float o3) {
        uint32_t a_off = (uint32_t)(c * 128 + (((lt0 >> 3) ^ (c & 7)) << 4) + ((lt0 & 4) << 1));
        *reinterpret_cast<uint2*>(sm + off + a_off) =
            make_uint2(pack_h(o0, o1), pack_h(o2, o3));
    };

    // ---- fused LN0 + LN1(sig*x): x -> t (X in place) and y1 (BA)
    {
        float4 xv[8];
        float4 s1 = make_float4(0,0,0,0), s2 = make_float4(0,0,0,0);
        #pragma unroll
        for (int k = 0; k < 8; k++) {
            xv[k] = *reinterpret_cast<const float4*>(&X[XI(part * 8 + k) + lt0]);
            s1.x += xv[k].x; s1.y += xv[k].y; s1.z += xv[k].z; s1.w += xv[k].w;
            s2.x += xv[k].x*xv[k].x; s2.y += xv[k].y*xv[k].y;
            s2.z += xv[k].z*xv[k].z; s2.w += xv[k].w*xv[k].w;
        }
        s1 = red16(s1); s2 = red16(s2);
        float4 mu, rs;
        mu.x = s1.x*(1.f/C); mu.y = s1.y*(1.f/C); mu.z = s1.z*(1.f/C); mu.w = s1.w*(1.f/C);
        rs.x = rsqrtf(s2.x*(1.f/C) - mu.x*mu.x + 1e-5f);
        rs.y = rsqrtf(s2.y*(1.f/C) - mu.y*mu.y + 1e-5f);
        rs.z = rsqrtf(s2.z*(1.f/C) - mu.z*mu.z + 1e-5f);
        rs.w = rsqrtf(s2.w*(1.f/C) - mu.w*mu.w + 1e-5f);
        float4 t1 = make_float4(0,0,0,0), t2 = make_float4(0,0,0,0);
        #pragma unroll
        for (int k = 0; k < 8; k++) {
            int c = part * 8 + k;
            float gg = __ldg(ln0_g + c), bbv = __ldg(ln0_b + c);
            xv[k].x = (xv[k].x - mu.x) * rs.x * gg + bbv;
            xv[k].y = (xv[k].y - mu.y) * rs.y * gg + bbv;
            xv[k].z = (xv[k].z - mu.z) * rs.z * gg + bbv;
            xv[k].w = (xv[k].w - mu.w) * rs.w * gg + bbv;
            *reinterpret_cast<float4*>(&X[XI(c) + lt0]) = xv[k];
            t1.x += xv[k].x; t1.y += xv[k].y; t1.z += xv[k].z; t1.w += xv[k].w;
            t2.x += xv[k].x*xv[k].x; t2.y += xv[k].y*xv[k].y;
            t2.z += xv[k].z*xv[k].z; t2.w += xv[k].w*xv[k].w;
        }
        t1 = red16(t1); t2 = red16(t2);
        mu.x = t1.x*(1.f/C); mu.y = t1.y*(1.f/C); mu.z = t1.z*(1.f/C); mu.w = t1.w*(1.f/C);
        rs.x = rsqrtf(t2.x*(1.f/C) - mu.x*mu.x + 1e-5f);
        rs.y = rsqrtf(t2.y*(1.f/C) - mu.y*mu.y + 1e-5f);
        rs.z = rsqrtf(t2.z*(1.f/C) - mu.z*mu.z + 1e-5f);
        rs.w = rsqrtf(t2.w*(1.f/C) - mu.w*mu.w + 1e-5f);
        #pragma unroll
        for (int k = 0; k < 8; k++) {
            int c = part * 8 + k;
            float gg = __ldg(ln1_g + c), bbv = __ldg(ln1_b + c);
            float o0 = (xv[k].x - mu.x) * rs.x * gg + bbv;
            float o1 = (xv[k].y - mu.y) * rs.y * gg + bbv;
            float o2 = (xv[k].z - mu.z) * rs.z * gg + bbv;
            float o3 = (xv[k].w - mu.w) * rs.w * gg + bbv;
            o0 *= sigm(o0); o1 *= sigm(o1); o2 *= sigm(o2); o3 *= sigm(o3);
            bstore(OFF_BA, c, o0, o1, o2, o3);
        }
    }
    __syncthreads();

    const unsigned char* wf = g_wfrag;
    const int c0 = wid * 16 + (lane >> 2);
    const int nb = (lane & 3) * 2;
    auto wptr = [&](int q) { return wf + (size_t)(q * 64 + wid) * 512 + (size_t)lane * 16; };

    // swizzled fp16 k-tile store for this thread's (nt, rows c0/c0+8) slice
    auto kstore = [&](char* bk, int nt, float a0, float a1, float a2, float a3) {
        uint32_t a_off  = (uint32_t)((nt ^ (c0 & 7)) << 4) + (uint32_t)((lane & 3) * 4);
        uint32_t a_off8 = (uint32_t)((nt ^ ((c0 + 8) & 7)) << 4) + (uint32_t)((lane & 3) * 4);
        *reinterpret_cast<uint32_t*>(bk + c0 * 128 + a_off)        = pack_h(a0, a1);
        *reinterpret_cast<uint32_t*>(bk + (c0 + 8) * 128 + a_off8) = pack_h(a2, a3);
    };
    auto relu2 = [](float v) { return v > 0.f ? v * v : 0.f; };

    float acc[8][4];

    // ---- att = Wout @ y1s ; X += att
    zero8(acc);
    gemm16(acc, wptr(0), smb + OFF_BA, lane);
    #pragma unroll
    for (int nt = 0; nt < 8; nt++) {
        int n = nt * 8 + nb;
        float2* p0 = reinterpret_cast<float2*>(&X[XI(c0) + n]);
        float2* p1 = reinterpret_cast<float2*>(&X[XI(c0 + 8) + n]);
        float2 v0 = *p0, v1 = *p1;
        v0.x += acc[nt][0]; v0.y += acc[nt][1];
        v1.x += acc[nt][2]; v1.y += acc[nt][3];
        *p0 = v0; *p1 = v1;
    }
    __syncthreads();

    // ---- LN2: X -> y2 (BA)
    {
        float4 xv[8];
        float4 s1 = make_float4(0,0,0,0), s2 = make_float4(0,0,0,0);
        #pragma unroll
        for (int k = 0; k < 8; k++) {
            xv[k] = *reinterpret_cast<const float4*>(&X[XI(part * 8 + k) + lt0]);
            s1.x += xv[k].x; s1.y += xv[k].y; s1.z += xv[k].z; s1.w += xv[k].w;
            s2.x += xv[k].x*xv[k].x; s2.y += xv[k].y*xv[k].y;
            s2.z += xv[k].z*xv[k].z; s2.w += xv[k].w*xv[k].w;
        }
        s1 = red16(s1); s2 = red16(s2);
        float4 mu, rs;
        mu.x = s1.x*(1.f/C); mu.y = s1.y*(1.f/C); mu.z = s1.z*(1.f/C); mu.w = s1.w*(1.f/C);
        rs.x = rsqrtf(s2.x*(1.f/C) - mu.x*mu.x + 1e-5f);
        rs.y = rsqrtf(s2.y*(1.f/C) - mu.y*mu.y + 1e-5f);
        rs.z = rsqrtf(s2.z*(1.f/C) - mu.z*mu.z + 1e-5f);
        rs.w = rsqrtf(s2.w*(1.f/C) - mu.w*mu.w + 1e-5f);
        #pragma unroll
        for (int k = 0; k < 8; k++) {
            int c = part * 8 + k;
            float gg = __ldg(ln2_g + c), bbv = __ldg(ln2_b + c);
            bstore(OFF_BA, c,
                (xv[k].x - mu.x) * rs.x * gg + bbv,
                (xv[k].y - mu.y) * rs.y * gg + bbv,
                (xv[k].z - mu.z) * rs.z * gg + bbv,
                (xv[k].w - mu.w) * rs.w * gg + bbv);
        }
    }
    __syncthreads();

    // ---- wht = Wwhiten @ y2 -> BW (fp16)
    zero8(acc);
    gemm16(acc, wptr(1), smb + OFF_BA, lane);
    #pragma unroll
    for (int nt = 0; nt < 8; nt++)
        kstore(sm + OFF_BW, nt, acc[nt][0], acc[nt][1], acc[nt][2], acc[nt][3]);
    __syncthreads();   // BW visible; all BA reads (whiten) complete

    // ---- recep + key0 fused (one BW pass): r -> 16 packed regs, k0 -> BA
    float accR[8][4];
    zero8(accR); zero8(acc);
    gemm16x2(accR, acc, wptr(2), wptr(3), smb + OFF_BW, lane);
    uint32_t rpk[16];
    #pragma unroll
    for (int nt = 0; nt < 8; nt++) {
        rpk[2*nt]   = pack_h(sigm(accR[nt][0]), sigm(accR[nt][1]));
        rpk[2*nt+1] = pack_h(sigm(accR[nt][2]), sigm(accR[nt][3]));
    }
    #pragma unroll
    for (int nt = 0; nt < 8; nt++)
        kstore(sm + OFF_BA, nt,
               relu2(acc[nt][0]), relu2(acc[nt][1]), relu2(acc[nt][2]), relu2(acc[nt][3]));

    // ---- key1 + key2 fused (one BW pass): k1 -> BK, k2 -> K2
    zero8(accR); zero8(acc);
    gemm16x2(acc, accR, wptr(4), wptr(5), smb + OFF_BW, lane);
    #pragma unroll
    for (int nt = 0; nt < 8; nt++)
        kstore(sm + OFF_BK, nt,
               relu2(acc[nt][0]), relu2(acc[nt][1]), relu2(acc[nt][2]), relu2(acc[nt][3]));
    #pragma unroll
    for (int nt = 0; nt < 8; nt++)
        kstore(sm + OFF_K2, nt,
               relu2(accR[nt][0]), relu2(accR[nt][1]), relu2(accR[nt][2]), relu2(accR[nt][3]));

    // ---- key3: last BW read; then k3 overwrites BW
    zero8(acc);
    gemm16(acc, wptr(6), smb + OFF_BW, lane);
    __syncthreads();   // all warps done reading BW; k0/k1/k2 stores visible
    #pragma unroll
    for (int nt = 0; nt < 8; nt++)
        kstore(sm + OFF_BW, nt,
               relu2(acc[nt][0]), relu2(acc[nt][1]), relu2(acc[nt][2]), relu2(acc[nt][3]));

    // ---- kv = sum of 4 value gemms (k3's BW needs one more sync, placed after K2 pass)
    float accKV[8][4];
    zero8(accKV);
    gemm16(accKV, wptr(7), smb + OFF_BA, lane);
    gemm16(accKV, wptr(8), smb + OFF_BK, lane);
    gemm16(accKV, wptr(9), smb + OFF_K2, lane);
    __syncthreads();   // all warps' k3 stores to BW visible
    gemm16(accKV, wptr(10), smb + OFF_BW, lane);

    // ---- out = 2 * (X + r * kv)   (r from registers)
    #pragma unroll
    for (int nt = 0; nt < 8; nt++) {
        int n = nt * 8 + nb;
        float2 r0 = unpack_h(rpk[2*nt]);
        float2 r1 = unpack_h(rpk[2*nt+1]);
        float2 x0 = *reinterpret_cast<float2*>(&X[XI(c0) + n]);
        float2 x1 = *reinterpret_cast<float2*>(&X[XI(c0 + 8) + n]);
        float2 o0, o1;
        o0.x = 2.0f * (x0.x + r0.x * accKV[nt][0]);
        o0.y = 2.0f * (x0.y + r0.y * accKV[nt][1]);
        o1.x = 2.0f * (x1.x + r1.x * accKV[nt][2]);
        o1.y = 2.0f * (x1.y + r1.y * accKV[nt][3]);
        *reinterpret_cast<float2*>(&ob[c0 * HW + n]) = o0;
        *reinterpret_cast<float2*>(&ob[(c0 + 8) * HW + n]) = o1;
    }
}

extern "C" void kernel_launch(void* const* d_in, const int* in_sizes, int n_in,
                              void* d_out, int out_size)
{
    const float* x       = (const float*)d_in[0];
    const float* ln0_g   = (const float*)d_in[1];
    const float* ln0_b   = (const float*)d_in[2];
    const float* ln1_g   = (const float*)d_in[3];
    const float* ln1_b   = (const float*)d_in[4];
    const float* ln2_g   = (const float*)d_in[5];
    const float* ln2_b   = (const float*)d_in[6];
    const float* Wout    = (const float*)d_in[7];
    const float* Wwhiten = (const float*)d_in[8];
    const float* Wkey    = (const float*)d_in[9];
    const float* Wrecep  = (const float*)d_in[10];
    const float* Wvalue  = (const float*)d_in[11];
    float* out = (float*)d_out;

    prep_kernel<<<88, NTH>>>(Wout, Wwhiten, Wkey, Wrecep, Wvalue);

    cudaFuncSetAttribute(rwkv_mma_kernel,
                         cudaFuncAttributeMaxDynamicSharedMemorySize, SMEM_TOT);
    rwkv_mma_kernel<<<1024, NTH, SMEM_TOT>>>(
        x, ln0_g, ln0_b, ln1_g, ln1_b, ln2_g, ln2_b, out);
}

// round 15
// speedup vs baseline: 1.4325x; 1.4325x over previous
#include <cuda_runtime.h>
#include <cuda_fp16.h>
#include <cstdint>

#define C    128
#define NTH  256
#define HW   16384

#define WSZ 360448u    // 11 chunks * 32768B fp16-hi fragment images
__device__ __align__(16) unsigned char g_wfrag[WSZ];

// ---- smem layout (bytes) ----
#define OFF_X    0                      // fp32 X, skewed layout, ~35KB
#define OFF_BA   35072                  // act tile (y1/y2) / k0,k2 buf
#define OFF_BW   (OFF_BA + 16384)       // wht tile
#define OFF_BK   (OFF_BW + 16384)       // k1,k3 buf
#define OFF_RS   (OFF_BK + 16384)       // sigmoid(r) fp16 [128][64]
#define SMEM_TOT (OFF_RS + 16384)       // 100608

// X row index: stride 68 floats + 16B skew per 8 rows (bank-spread for LN mapping)
__device__ __forceinline__ int XI(int c) { return c * 68 + ((c >> 3) << 2); }

// ---- helpers ----
__device__ __forceinline__ uint32_t pack_h(float lo, float hi) {
    uint32_t d;
    asm("cvt.rn.f16x2.f32 %0, %1, %2;" : "=r"(d) : "f"(hi), "f"(lo));
    return d;
}
__device__ __forceinline__ float2 unpack_h(uint32_t v) {
    __half2 h = *reinterpret_cast<__half2*>(&v);
    return __half22float2(h);
}
__device__ __forceinline__ float sigm(float v) { return 1.0f / (1.0f + __expf(-v)); }

__device__ __forceinline__ void ldsm4t(uint32_t& r0, uint32_t& r1, uint32_t& r2,
                                       uint32_t& r3, uint32_t addr) {
    asm volatile("ldmatrix.sync.aligned.m8n8.x4.trans.shared.b16 {%0,%1,%2,%3}, [%4];"
                 : "=r"(r0), "=r"(r1), "=r"(r2), "=r"(r3) : "r"(addr));
}
__device__ __forceinline__ void mma16(float* d, const uint4& a, uint32_t b0, uint32_t b1) {
    asm volatile("mma.sync.aligned.m16n8k16.row.col.f32.f16.f16.f32 "
                 "{%0,%1,%2,%3}, {%4,%5,%6,%7}, {%8,%9}, {%0,%1,%2,%3};"
                 : "+f"(d[0]), "+f"(d[1]), "+f"(d[2]), "+f"(d[3])
                 : "r"(a.x), "r"(a.y), "r"(a.z), "r"(a.w), "r"(b0), "r"(b1));
}
__device__ __forceinline__ void zero8(float (*a)[4]) {
    #pragma unroll
    for (int i = 0; i < 8; i++)
        #pragma unroll
        for (int j = 0; j < 4; j++) a[i][j] = 0.f;
}
// sum across the 16 channel-parts of one token group (16-lane segment)
__device__ __forceinline__ float4 red16(float4 v) {
    #pragma unroll
    for (int m = 1; m <= 8; m <<= 1) {
        v.x += __shfl_xor_sync(0xffffffffu, v.x, m, 16);
        v.y += __shfl_xor_sync(0xffffffffu, v.y, m, 16);
        v.z += __shfl_xor_sync(0xffffffffu, v.z, m, 16);
        v.w += __shfl_xor_sync(0xffffffffu, v.w, m, 16);
    }
    return v;
}

// gemm: D[16 out x 64 tok] per warp; single weight term; proven schedule (unroll 2).
__device__ __forceinline__ void gemm16(float (*acc)[4],
    const unsigned char* __restrict__ wfh, uint32_t bh, int lane)
{
    const int grp  = lane >> 3, r8 = lane & 7;
    const int kadd = (grp & 1) * 8 + r8;
    const int cgrp = grp >> 1;
    uint32_t coff[4];
    #pragma unroll
    for (int ntp = 0; ntp < 4; ntp++)
        coff[ntp] = (uint32_t)(((ntp * 2 + cgrp) ^ r8) << 4);
    #pragma unroll 2
    for (int kt = 0; kt < 8; kt++) {
        uint4 A = *reinterpret_cast<const uint4*>(wfh + kt * 4096);
        uint32_t rowb = bh + (uint32_t)((kt * 16 + kadd) * 128);
        uint32_t b[16];
        #pragma unroll
        for (int ntp = 0; ntp < 4; ntp++)
            ldsm4t(b[4*ntp], b[4*ntp+1], b[4*ntp+2], b[4*ntp+3], rowb + coff[ntp]);
        #pragma unroll
        for (int ntp = 0; ntp < 4; ntp++) {
            mma16(acc[2*ntp],   A, b[4*ntp],   b[4*ntp+1]);
            mma16(acc[2*ntp+1], A, b[4*ntp+2], b[4*ntp+3]);
        }
    }
}

// ---- prep: fp32 weights -> fragment-ordered fp16 hi images ----
// chunk q: 0=Wout 1=Wwhiten 2=Wrecep 3..6=Wkey rows ch*128.. 7..10=Wvalue cols ch*128..
__global__ void __launch_bounds__(NTH) prep_kernel(
    const float* __restrict__ Wout, const float* __restrict__ Wwh,
    const float* __restrict__ Wkey, const float* __restrict__ Wrec,
    const float* __restrict__ Wval)
{
    int e = blockIdx.x * NTH + threadIdx.x;
    if (e >= 11 * 64 * 32) return;
    int lane = e & 31, mt = (e >> 5) & 7, kt = (e >> 8) & 7, q = e >> 11;
    int r  = lane >> 2;
    int cb = (lane & 3) * 2;
    float v[8];
    #pragma unroll
    for (int j = 0; j < 8; j++) {
        int row = mt * 16 + r + ((j >> 1) & 1) * 8;
        int col = kt * 16 + cb + (j >> 2) * 8 + (j & 1);
        float w;
        if (q == 0)      w = Wout[row * 128 + col];
        else if (q == 1) w = Wwh[row * 128 + col];
        else if (q == 2) w = Wrec[row * 128 + col];
        else if (q <= 6) w = Wkey[((q - 3) * 128 + row) * 128 + col];
        else             w = Wval[row * 512 + (q - 7) * 128 + col];
        v[j] = w;
    }
    uint4 hi;
    uint32_t* hp = &hi.x;
    #pragma unroll
    for (int p = 0; p < 4; p++)
        hp[p] = pack_h(v[2*p], v[2*p+1]);
    size_t off = (size_t)(((q * 8 + kt) * 8 + mt) * 32 + lane) * 16;
    *reinterpret_cast<uint4*>(g_wfrag + off) = hi;
}

// ---- main ----
__global__ void __launch_bounds__(NTH, 2) rwkv_mma_kernel(
    const float* __restrict__ x,
    const float* __restrict__ ln0_g, const float* __restrict__ ln0_b,
    const float* __restrict__ ln1_g, const float* __restrict__ ln1_b,
    const float* __restrict__ ln2_g, const float* __restrict__ ln2_b,
    float* __restrict__ out)
{
    extern __shared__ char sm[];
    const int tid  = threadIdx.x;
    const int wid  = tid >> 5;
    const int lane = tid & 31;
    const uint32_t smb = (uint32_t)__cvta_generic_to_shared(sm);

    const int tile = blockIdx.x;
    const int b    = tile >> 8;
    const int hw0  = (tile & 255) * 64;
    const float* xb = x   + (size_t)b * C * HW + hw0;
    float*       ob = out + (size_t)b * C * HW + hw0;

    float* X = (float*)(sm + OFF_X);

    // load X tile (float4 over tokens, 16 threads per channel row)
    #pragma unroll
    for (int k = 0; k < 8; k++) {
        int idx = tid + k * NTH;
        int c = idx >> 4, t = (idx & 15) * 4;
        *reinterpret_cast<float4*>(&X[XI(c) + t]) =
            *reinterpret_cast<const float4*>(&xb[c * HW + t]);
    }
    __syncthreads();

    // LN mapping: thread = tg*16 + part; part owns 8 channels, tg owns 4 tokens.
    const int part = tid & 15;
    const int tg   = tid >> 4;
    const int lt0  = tg * 4;

    auto bstore = [&](int off, int c, float o0, float o1, float o2, float o3) {
        uint32_t a_off = (uint32_t)(c * 128 + (((lt0 >> 3) ^ (c & 7)) << 4) + ((lt0 & 4) << 1));
        *reinterpret_cast<uint2*>(sm + off + a_off) =
            make_uint2(pack_h(o0, o1), pack_h(o2, o3));
    };

    // ---- fused LN0 + LN1(sig*x): x -> t (X in place) and y1 (BA)
    {
        float4 xv[8];
        float4 s1 = make_float4(0,0,0,0), s2 = make_float4(0,0,0,0);
        #pragma unroll
        for (int k = 0; k < 8; k++) {
            xv[k] = *reinterpret_cast<const float4*>(&X[XI(part * 8 + k) + lt0]);
            s1.x += xv[k].x; s1.y += xv[k].y; s1.z += xv[k].z; s1.w += xv[k].w;
            s2.x += xv[k].x*xv[k].x; s2.y += xv[k].y*xv[k].y;
            s2.z += xv[k].z*xv[k].z; s2.w += xv[k].w*xv[k].w;
        }
        s1 = red16(s1); s2 = red16(s2);
        float4 mu, rs;
        mu.x = s1.x*(1.f/C); mu.y = s1.y*(1.f/C); mu.z = s1.z*(1.f/C); mu.w = s1.w*(1.f/C);
        rs.x = rsqrtf(s2.x*(1.f/C) - mu.x*mu.x + 1e-5f);
        rs.y = rsqrtf(s2.y*(1.f/C) - mu.y*mu.y + 1e-5f);
        rs.z = rsqrtf(s2.z*(1.f/C) - mu.z*mu.z + 1e-5f);
        rs.w = rsqrtf(s2.w*(1.f/C) - mu.w*mu.w + 1e-5f);
        float4 t1 = make_float4(0,0,0,0), t2 = make_float4(0,0,0,0);
        #pragma unroll
        for (int k = 0; k < 8; k++) {
            int c = part * 8 + k;
            float gg = __ldg(ln0_g + c), bbv = __ldg(ln0_b + c);
            xv[k].x = (xv[k].x - mu.x) * rs.x * gg + bbv;
            xv[k].y = (xv[k].y - mu.y) * rs.y * gg + bbv;
            xv[k].z = (xv[k].z - mu.z) * rs.z * gg + bbv;
            xv[k].w = (xv[k].w - mu.w) * rs.w * gg + bbv;
            *reinterpret_cast<float4*>(&X[XI(c) + lt0]) = xv[k];
            t1.x += xv[k].x; t1.y += xv[k].y; t1.z += xv[k].z; t1.w += xv[k].w;
            t2.x += xv[k].x*xv[k].x; t2.y += xv[k].y*xv[k].y;
            t2.z += xv[k].z*xv[k].z; t2.w += xv[k].w*xv[k].w;
        }
        t1 = red16(t1); t2 = red16(t2);
        mu.x = t1.x*(1.f/C); mu.y = t1.y*(1.f/C); mu.z = t1.z*(1.f/C); mu.w = t1.w*(1.f/C);
        rs.x = rsqrtf(t2.x*(1.f/C) - mu.x*mu.x + 1e-5f);
        rs.y = rsqrtf(t2.y*(1.f/C) - mu.y*mu.y + 1e-5f);
        rs.z = rsqrtf(t2.z*(1.f/C) - mu.z*mu.z + 1e-5f);
        rs.w = rsqrtf(t2.w*(1.f/C) - mu.w*mu.w + 1e-5f);
        #pragma unroll
        for (int k = 0; k < 8; k++) {
            int c = part * 8 + k;
            float gg = __ldg(ln1_g + c), bbv = __ldg(ln1_b + c);
            float o0 = (xv[k].x - mu.x) * rs.x * gg + bbv;
            float o1 = (xv[k].y - mu.y) * rs.y * gg + bbv;
            float o2 = (xv[k].z - mu.z) * rs.z * gg + bbv;
            float o3 = (xv[k].w - mu.w) * rs.w * gg + bbv;
            o0 *= sigm(o0); o1 *= sigm(o1); o2 *= sigm(o2); o3 *= sigm(o3);
            bstore(OFF_BA, c, o0, o1, o2, o3);
        }
    }
    __syncthreads();

    const unsigned char* wf = g_wfrag;
    const int c0 = wid * 16 + (lane >> 2);
    const int nb = (lane & 3) * 2;
    auto wptr = [&](int q) { return wf + (size_t)(q * 64 + wid) * 512 + (size_t)lane * 16; };

    // swizzled fp16 k-tile store for this thread's (nt, rows c0/c0+8) slice
    auto kstore = [&](char* bk, int nt, float a0, float a1, float a2, float a3) {
        uint32_t a_off  = (uint32_t)((nt ^ (c0 & 7)) << 4) + (uint32_t)((lane & 3) * 4);
        uint32_t a_off8 = (uint32_t)((nt ^ ((c0 + 8) & 7)) << 4) + (uint32_t)((lane & 3) * 4);
        *reinterpret_cast<uint32_t*>(bk + c0 * 128 + a_off)        = pack_h(a0, a1);
        *reinterpret_cast<uint32_t*>(bk + (c0 + 8) * 128 + a_off8) = pack_h(a2, a3);
    };
    auto relu2 = [](float v) { return v > 0.f ? v * v : 0.f; };

    float acc[8][4];

    // ---- att = Wout @ y1s ; X += att
    zero8(acc);
    gemm16(acc, wptr(0), smb + OFF_BA, lane);
    #pragma unroll
    for (int nt = 0; nt < 8; nt++) {
        int n = nt * 8 + nb;
        float2* p0 = reinterpret_cast<float2*>(&X[XI(c0) + n]);
        float2* p1 = reinterpret_cast<float2*>(&X[XI(c0 + 8) + n]);
        float2 v0 = *p0, v1 = *p1;
        v0.x += acc[nt][0]; v0.y += acc[nt][1];
        v1.x += acc[nt][2]; v1.y += acc[nt][3];
        *p0 = v0; *p1 = v1;
    }
    __syncthreads();

    // ---- LN2: X -> y2 (BA)
    {
        float4 xv[8];
        float4 s1 = make_float4(0,0,0,0), s2 = make_float4(0,0,0,0);
        #pragma unroll
        for (int k = 0; k < 8; k++) {
            xv[k] = *reinterpret_cast<const float4*>(&X[XI(part * 8 + k) + lt0]);
            s1.x += xv[k].x; s1.y += xv[k].y; s1.z += xv[k].z; s1.w += xv[k].w;
            s2.x += xv[k].x*xv[k].x; s2.y += xv[k].y*xv[k].y;
            s2.z += xv[k].z*xv[k].z; s2.w += xv[k].w*xv[k].w;
        }
        s1 = red16(s1); s2 = red16(s2);
        float4 mu, rs;
        mu.x = s1.x*(1.f/C); mu.y = s1.y*(1.f/C); mu.z = s1.z*(1.f/C); mu.w = s1.w*(1.f/C);
        rs.x = rsqrtf(s2.x*(1.f/C) - mu.x*mu.x + 1e-5f);
        rs.y = rsqrtf(s2.y*(1.f/C) - mu.y*mu.y + 1e-5f);
        rs.z = rsqrtf(s2.z*(1.f/C) - mu.z*mu.z + 1e-5f);
        rs.w = rsqrtf(s2.w*(1.f/C) - mu.w*mu.w + 1e-5f);
        #pragma unroll
        for (int k = 0; k < 8; k++) {
            int c = part * 8 + k;
            float gg = __ldg(ln2_g + c), bbv = __ldg(ln2_b + c);
            bstore(OFF_BA, c,
                (xv[k].x - mu.x) * rs.x * gg + bbv,
                (xv[k].y - mu.y) * rs.y * gg + bbv,
                (xv[k].z - mu.z) * rs.z * gg + bbv,
                (xv[k].w - mu.w) * rs.w * gg + bbv);
        }
    }
    __syncthreads();

    // ---- wht = Wwhiten @ y2 -> BW (fp16)
    zero8(acc);
    gemm16(acc, wptr(1), smb + OFF_BA, lane);
    #pragma unroll
    for (int nt = 0; nt < 8; nt++)
        kstore(sm + OFF_BW, nt, acc[nt][0], acc[nt][1], acc[nt][2], acc[nt][3]);
    __syncthreads();   // BW visible; all BA reads (whiten) complete

    // ---- recep + key0 + key1: three BW-only gemms, no syncs between
    // r -> RS (same-thread readback later), k0 -> BA, k1 -> BK
    zero8(acc);
    gemm16(acc, wptr(2), smb + OFF_BW, lane);
    #pragma unroll
    for (int nt = 0; nt < 8; nt++) {
        int n = nt * 8 + nb;
        *reinterpret_cast<uint32_t*>(sm + OFF_RS + c0 * 128 + n * 2) =
            pack_h(sigm(acc[nt][0]), sigm(acc[nt][1]));
        *reinterpret_cast<uint32_t*>(sm + OFF_RS + (c0 + 8) * 128 + n * 2) =
            pack_h(sigm(acc[nt][2]), sigm(acc[nt][3]));
    }
    zero8(acc);
    gemm16(acc, wptr(3), smb + OFF_BW, lane);
    #pragma unroll
    for (int nt = 0; nt < 8; nt++)
        kstore(sm + OFF_BA, nt,
               relu2(acc[nt][0]), relu2(acc[nt][1]), relu2(acc[nt][2]), relu2(acc[nt][3]));
    zero8(acc);
    gemm16(acc, wptr(4), smb + OFF_BW, lane);
    #pragma unroll
    for (int nt = 0; nt < 8; nt++)
        kstore(sm + OFF_BK, nt,
               relu2(acc[nt][0]), relu2(acc[nt][1]), relu2(acc[nt][2]), relu2(acc[nt][3]));
    __syncthreads();   // k0/k1 visible

    // ---- value0 + value1 (back-to-back, independent B tiles)
    float accKV[8][4];
    zero8(accKV);
    gemm16(accKV, wptr(7), smb + OFF_BA, lane);
    gemm16(accKV, wptr(8), smb + OFF_BK, lane);
    __syncthreads();   // all BA/BK reads retired

    // ---- key2 -> BA, key3 -> BK (BW untouched until here)
    zero8(acc);
    gemm16(acc, wptr(5), smb + OFF_BW, lane);
    #pragma unroll
    for (int nt = 0; nt < 8; nt++)
        kstore(sm + OFF_BA, nt,
               relu2(acc[nt][0]), relu2(acc[nt][1]), relu2(acc[nt][2]), relu2(acc[nt][3]));
    zero8(acc);
    gemm16(acc, wptr(6), smb + OFF_BW, lane);
    #pragma unroll
    for (int nt = 0; nt < 8; nt++)
        kstore(sm + OFF_BK, nt,
               relu2(acc[nt][0]), relu2(acc[nt][1]), relu2(acc[nt][2]), relu2(acc[nt][3]));
    __syncthreads();   // k2/k3 visible

    // ---- value2 + value3
    gemm16(accKV, wptr(9),  smb + OFF_BA, lane);
    gemm16(accKV, wptr(10), smb + OFF_BK, lane);

    // ---- out = 2 * (X + r * kv)   (RS is same-thread readback)
    #pragma unroll
    for (int nt = 0; nt < 8; nt++) {
        int n = nt * 8 + nb;
        float2 r0 = unpack_h(*reinterpret_cast<uint32_t*>(sm + OFF_RS + c0 * 128 + n * 2));
        float2 r1 = unpack_h(*reinterpret_cast<uint32_t*>(sm + OFF_RS + (c0 + 8) * 128 + n * 2));
        float2 x0 = *reinterpret_cast<float2*>(&X[XI(c0) + n]);
        float2 x1 = *reinterpret_cast<float2*>(&X[XI(c0 + 8) + n]);
        float2 o0, o1;
        o0.x = 2.0f * (x0.x + r0.x * accKV[nt][0]);
        o0.y = 2.0f * (x0.y + r0.y * accKV[nt][1]);
        o1.x = 2.0f * (x1.x + r1.x * accKV[nt][2]);
        o1.y = 2.0f * (x1.y + r1.y * accKV[nt][3]);
        *reinterpret_cast<float2*>(&ob[c0 * HW + n]) = o0;
        *reinterpret_cast<float2*>(&ob[(c0 + 8) * HW + n]) = o1;
    }
}

extern "C" void kernel_launch(void* const* d_in, const int* in_sizes, int n_in,
                              void* d_out, int out_size)
{
    const float* x       = (const float*)d_in[0];
    const float* ln0_g   = (const float*)d_in[1];
    const float* ln0_b   = (const float*)d_in[2];
    const float* ln1_g   = (const float*)d_in[3];
    const float* ln1_b   = (const float*)d_in[4];
    const float* ln2_g   = (const float*)d_in[5];
    const float* ln2_b   = (const float*)d_in[6];
    const float* Wout    = (const float*)d_in[7];
    const float* Wwhiten = (const float*)d_in[8];
    const float* Wkey    = (const float*)d_in[9];
    const float* Wrecep  = (const float*)d_in[10];
    const float* Wvalue  = (const float*)d_in[11];
    float* out = (float*)d_out;

    prep_kernel<<<88, NTH>>>(Wout, Wwhiten, Wkey, Wrecep, Wvalue);

    cudaFuncSetAttribute(rwkv_mma_kernel,
                         cudaFuncAttributeMaxDynamicSharedMemorySize, SMEM_TOT);
    rwkv_mma_kernel<<<1024, NTH, SMEM_TOT>>>(
        x, ln0_g, ln0_b, ln1_g, ln1_b, ln2_g, ln2_b, out);
}

// round 17
// speedup vs baseline: 1.5068x; 1.0519x over previous
#include <cuda_runtime.h>
#include <cuda_fp16.h>
#include <cstdint>

#define C    128
#define NTH  256
#define HW   16384

#define WSZ 360448u    // 11 chunks * 32768B fp16-hi fragment images
__device__ __align__(16) unsigned char g_wfrag[WSZ];

// ---- smem layout (bytes) ----
#define OFF_X    0                      // fp32 X, skewed layout, ~35KB
#define OFF_BA   35072                  // act tile (y1/y2) / k0 buf
#define OFF_BW   (OFF_BA + 16384)       // wht tile, later k3 buf
#define OFF_BK   (OFF_BW + 16384)       // k1 buf
#define OFF_K2   (OFF_BK + 16384)       // k2 buf
#define SMEM_TOT (OFF_K2 + 16384)       // 100608

// X row index: stride 68 floats + 16B skew per 8 rows (bank-spread for LN mapping)
__device__ __forceinline__ int XI(int c) { return c * 68 + ((c >> 3) << 2); }

// ---- helpers ----
__device__ __forceinline__ uint32_t pack_h(float lo, float hi) {
    uint32_t d;
    asm("cvt.rn.f16x2.f32 %0, %1, %2;" : "=r"(d) : "f"(hi), "f"(lo));
    return d;
}
__device__ __forceinline__ float2 unpack_h(uint32_t v) {
    __half2 h = *reinterpret_cast<__half2*>(&v);
    return __half22float2(h);
}
__device__ __forceinline__ float sigm(float v) { return 1.0f / (1.0f + __expf(-v)); }

__device__ __forceinline__ void ldsm4t(uint32_t& r0, uint32_t& r1, uint32_t& r2,
                                       uint32_t& r3, uint32_t addr) {
    asm volatile("ldmatrix.sync.aligned.m8n8.x4.trans.shared.b16 {%0,%1,%2,%3}, [%4];"
                 : "=r"(r0), "=r"(r1), "=r"(r2), "=r"(r3) : "r"(addr));
}
__device__ __forceinline__ void mma16(float* d, const uint4& a, uint32_t b0, uint32_t b1) {
    asm volatile("mma.sync.aligned.m16n8k16.row.col.f32.f16.f16.f32 "
                 "{%0,%1,%2,%3}, {%4,%5,%6,%7}, {%8,%9}, {%0,%1,%2,%3};"
                 : "+f"(d[0]), "+f"(d[1]), "+f"(d[2]), "+f"(d[3])
                 : "r"(a.x), "r"(a.y), "r"(a.z), "r"(a.w), "r"(b0), "r"(b1));
}
// f16-accumulator variant: D/C are 2 regs {(c0,c1),(c2,c3)} — same element
// positions as the f32 form, packed pairwise.
__device__ __forceinline__ void mma16h(uint32_t* d, const uint4& a, uint32_t b0, uint32_t b1) {
    asm volatile("mma.sync.aligned.m16n8k16.row.col.f16.f16.f16.f16 "
                 "{%0,%1}, {%2,%3,%4,%5}, {%6,%7}, {%0,%1};"
                 : "+r"(d[0]), "+r"(d[1])
                 : "r"(a.x), "r"(a.y), "r"(a.z), "r"(a.w), "r"(b0), "r"(b1));
}
__device__ __forceinline__ void zero8(float (*a)[4]) {
    #pragma unroll
    for (int i = 0; i < 8; i++)
        #pragma unroll
        for (int j = 0; j < 4; j++) a[i][j] = 0.f;
}
__device__ __forceinline__ void zero8h(uint32_t (*a)[2]) {
    #pragma unroll
    for (int i = 0; i < 8; i++) { a[i][0] = 0u; a[i][1] = 0u; }
}
// sum across the 16 channel-parts of one token group (16-lane segment)
__device__ __forceinline__ float4 red16(float4 v) {
    #pragma unroll
    for (int m = 1; m <= 8; m <<= 1) {
        v.x += __shfl_xor_sync(0xffffffffu, v.x, m, 16);
        v.y += __shfl_xor_sync(0xffffffffu, v.y, m, 16);
        v.z += __shfl_xor_sync(0xffffffffu, v.z, m, 16);
        v.w += __shfl_xor_sync(0xffffffffu, v.w, m, 16);
    }
    return v;
}

struct BAddr { int kadd; uint32_t coff[4]; };
__device__ __forceinline__ BAddr baddr(int lane) {
    BAddr r;
    const int grp  = lane >> 3, r8 = lane & 7;
    r.kadd = (grp & 1) * 8 + r8;
    const int cgrp = grp >> 1;
    #pragma unroll
    for (int ntp = 0; ntp < 4; ntp++)
        r.coff[ntp] = (uint32_t)(((ntp * 2 + cgrp) ^ r8) << 4);
    return r;
}

// f32-D gemm: D[16 out x 64 tok]; proven schedule (unroll 2).
__device__ __forceinline__ void gemm16(float (*acc)[4],
    const unsigned char* __restrict__ wfh, uint32_t bh, int lane)
{
    BAddr ad = baddr(lane);
    #pragma unroll 2
    for (int kt = 0; kt < 8; kt++) {
        uint4 A = *reinterpret_cast<const uint4*>(wfh + kt * 4096);
        uint32_t rowb = bh + (uint32_t)((kt * 16 + ad.kadd) * 128);
        uint32_t b[16];
        #pragma unroll
        for (int ntp = 0; ntp < 4; ntp++)
            ldsm4t(b[4*ntp], b[4*ntp+1], b[4*ntp+2], b[4*ntp+3], rowb + ad.coff[ntp]);
        #pragma unroll
        for (int ntp = 0; ntp < 4; ntp++) {
            mma16(acc[2*ntp],   A, b[4*ntp],   b[4*ntp+1]);
            mma16(acc[2*ntp+1], A, b[4*ntp+2], b[4*ntp+3]);
        }
    }
}

// f16-D single gemm (16 acc regs).
__device__ __forceinline__ void gemm16h(uint32_t (*acc)[2],
    const unsigned char* __restrict__ wfh, uint32_t bh, int lane)
{
    BAddr ad = baddr(lane);
    #pragma unroll 2
    for (int kt = 0; kt < 8; kt++) {
        uint4 A = *reinterpret_cast<const uint4*>(wfh + kt * 4096);
        uint32_t rowb = bh + (uint32_t)((kt * 16 + ad.kadd) * 128);
        uint32_t b[16];
        #pragma unroll
        for (int ntp = 0; ntp < 4; ntp++)
            ldsm4t(b[4*ntp], b[4*ntp+1], b[4*ntp+2], b[4*ntp+3], rowb + ad.coff[ntp]);
        #pragma unroll
        for (int ntp = 0; ntp < 4; ntp++) {
            mma16h(acc[2*ntp],   A, b[4*ntp],   b[4*ntp+1]);
            mma16h(acc[2*ntp+1], A, b[4*ntp+2], b[4*ntp+3]);
        }
    }
}

// f16-D fused gemm: TWO weight chunks per B-tile read; 2x16 acc regs total
// (same RF cost as ONE f32 acc set — this is what makes fusion spill-free).
__device__ __forceinline__ void gemm16x2h(uint32_t (*accA)[2], uint32_t (*accB)[2],
    const unsigned char* __restrict__ wfA, const unsigned char* __restrict__ wfB,
    uint32_t bh, int lane)
{
    BAddr ad = baddr(lane);
    #pragma unroll 1
    for (int kt = 0; kt < 8; kt++) {
        uint4 A0 = *reinterpret_cast<const uint4*>(wfA + kt * 4096);
        uint4 A1 = *reinterpret_cast<const uint4*>(wfB + kt * 4096);
        uint32_t rowb = bh + (uint32_t)((kt * 16 + ad.kadd) * 128);
        uint32_t b[16];
        #pragma unroll
        for (int ntp = 0; ntp < 4; ntp++)
            ldsm4t(b[4*ntp], b[4*ntp+1], b[4*ntp+2], b[4*ntp+3], rowb + ad.coff[ntp]);
        #pragma unroll
        for (int ntp = 0; ntp < 4; ntp++) {
            mma16h(accA[2*ntp],   A0, b[4*ntp],   b[4*ntp+1]);
            mma16h(accA[2*ntp+1], A0, b[4*ntp+2], b[4*ntp+3]);
        }
        #pragma unroll
        for (int ntp = 0; ntp < 4; ntp++) {
            mma16h(accB[2*ntp],   A1, b[4*ntp],   b[4*ntp+1]);
            mma16h(accB[2*ntp+1], A1, b[4*ntp+2], b[4*ntp+3]);
        }
    }
}

// ---- prep: fp32 weights -> fragment-ordered fp16 hi images ----
// chunk q: 0=Wout 1=Wwhiten 2=Wrecep 3..6=Wkey rows ch*128.. 7..10=Wvalue cols ch*128..
__global__ void __launch_bounds__(NTH) prep_kernel(
    const float* __restrict__ Wout, const float* __restrict__ Wwh,
    const float* __restrict__ Wkey, const float* __restrict__ Wrec,
    const float* __restrict__ Wval)
{
    int e = blockIdx.x * NTH + threadIdx.x;
    if (e >= 11 * 64 * 32) return;
    int lane = e & 31, mt = (e >> 5) & 7, kt = (e >> 8) & 7, q = e >> 11;
    int r  = lane >> 2;
    int cb = (lane & 3) * 2;
    float v[8];
    #pragma unroll
    for (int j = 0; j < 8; j++) {
        int row = mt * 16 + r + ((j >> 1) & 1) * 8;
        int col = kt * 16 + cb + (j >> 2) * 8 + (j & 1);
        float w;
        if (q == 0)      w = Wout[row * 128 + col];
        else if (q == 1) w = Wwh[row * 128 + col];
        else if (q == 2) w = Wrec[row * 128 + col];
        else if (q <= 6) w = Wkey[((q - 3) * 128 + row) * 128 + col];
        else             w = Wval[row * 512 + (q - 7) * 128 + col];
        v[j] = w;
    }
    uint4 hi;
    uint32_t* hp = &hi.x;
    #pragma unroll
    for (int p = 0; p < 4; p++)
        hp[p] = pack_h(v[2*p], v[2*p+1]);
    size_t off = (size_t)(((q * 8 + kt) * 8 + mt) * 32 + lane) * 16;
    *reinterpret_cast<uint4*>(g_wfrag + off) = hi;
}

// ---- main ----
__global__ void __launch_bounds__(NTH, 2) rwkv_mma_kernel(
    const float* __restrict__ x,
    const float* __restrict__ ln0_g, const float* __restrict__ ln0_b,
    const float* __restrict__ ln1_g, const float* __restrict__ ln1_b,
    const float* __restrict__ ln2_g, const float* __restrict__ ln2_b,
    float* __restrict__ out)
{
    extern __shared__ char sm[];
    const int tid  = threadIdx.x;
    const int wid  = tid >> 5;
    const int lane = tid & 31;
    const uint32_t smb = (uint32_t)__cvta_generic_to_shared(sm);

    const int tile = blockIdx.x;
    const int b    = tile >> 8;
    const int hw0  = (tile & 255) * 64;
    const float* xb = x   + (size_t)b * C * HW + hw0;
    float*       ob = out + (size_t)b * C * HW + hw0;

    float* X = (float*)(sm + OFF_X);

    // load X tile (float4 over tokens, 16 threads per channel row)
    #pragma unroll
    for (int k = 0; k < 8; k++) {
        int idx = tid + k * NTH;
        int c = idx >> 4, t = (idx & 15) * 4;
        *reinterpret_cast<float4*>(&X[XI(c) + t]) =
            *reinterpret_cast<const float4*>(&xb[c * HW + t]);
    }
    __syncthreads();

    // LN mapping: thread = tg*16 + part; part owns 8 channels, tg owns 4 tokens.
    const int part = tid & 15;
    const int tg   = tid >> 4;
    const int lt0  = tg * 4;

    auto bstore = [&](int off, int c, float o0, float o1, float o2, float o3) {
        uint32_t a_off = (uint32_t)(c * 128 + (((lt0 >> 3) ^ (c & 7)) << 4) + ((lt0 & 4) << 1));
        *reinterpret_cast<uint2*>(sm + off + a_off) =
            make_uint2(pack_h(o0, o1), pack_h(o2, o3));
    };

    // ---- fused LN0 + LN1(sig*x): x -> t (X in place) and y1 (BA)
    {
        float4 xv[8];
        float4 s1 = make_float4(0,0,0,0), s2 = make_float4(0,0,0,0);
        #pragma unroll
        for (int k = 0; k < 8; k++) {
            xv[k] = *reinterpret_cast<const float4*>(&X[XI(part * 8 + k) + lt0]);
            s1.x += xv[k].x; s1.y += xv[k].y; s1.z += xv[k].z; s1.w += xv[k].w;
            s2.x += xv[k].x*xv[k].x; s2.y += xv[k].y*xv[k].y;
            s2.z += xv[k].z*xv[k].z; s2.w += xv[k].w*xv[k].w;
        }
        s1 = red16(s1); s2 = red16(s2);
        float4 mu, rs;
        mu.x = s1.x*(1.f/C); mu.y = s1.y*(1.f/C); mu.z = s1.z*(1.f/C); mu.w = s1.w*(1.f/C);
        rs.x = rsqrtf(s2.x*(1.f/C) - mu.x*mu.x + 1e-5f);
        rs.y = rsqrtf(s2.y*(1.f/C) - mu.y*mu.y + 1e-5f);
        rs.z = rsqrtf(s2.z*(1.f/C) - mu.z*mu.z + 1e-5f);
        rs.w = rsqrtf(s2.w*(1.f/C) - mu.w*mu.w + 1e-5f);
        float4 t1 = make_float4(0,0,0,0), t2 = make_float4(0,0,0,0);
        #pragma unroll
        for (int k = 0; k < 8; k++) {
            int c = part * 8 + k;
            float gg = __ldg(ln0_g + c), bbv = __ldg(ln0_b + c);
            xv[k].x = (xv[k].x - mu.x) * rs.x * gg + bbv;
            xv[k].y = (xv[k].y - mu.y) * rs.y * gg + bbv;
            xv[k].z = (xv[k].z - mu.z) * rs.z * gg + bbv;
            xv[k].w = (xv[k].w - mu.w) * rs.w * gg + bbv;
            *reinterpret_cast<float4*>(&X[XI(c) + lt0]) = xv[k];
            t1.x += xv[k].x; t1.y += xv[k].y; t1.z += xv[k].z; t1.w += xv[k].w;
            t2.x += xv[k].x*xv[k].x; t2.y += xv[k].y*xv[k].y;
            t2.z += xv[k].z*xv[k].z; t2.w += xv[k].w*xv[k].w;
        }
        t1 = red16(t1); t2 = red16(t2);
        mu.x = t1.x*(1.f/C); mu.y = t1.y*(1.f/C); mu.z = t1.z*(1.f/C); mu.w = t1.w*(1.f/C);
        rs.x = rsqrtf(t2.x*(1.f/C) - mu.x*mu.x + 1e-5f);
        rs.y = rsqrtf(t2.y*(1.f/C) - mu.y*mu.y + 1e-5f);
        rs.z = rsqrtf(t2.z*(1.f/C) - mu.z*mu.z + 1e-5f);
        rs.w = rsqrtf(t2.w*(1.f/C) - mu.w*mu.w + 1e-5f);
        #pragma unroll
        for (int k = 0; k < 8; k++) {
            int c = part * 8 + k;
            float gg = __ldg(ln1_g + c), bbv = __ldg(ln1_b + c);
            float o0 = (xv[k].x - mu.x) * rs.x * gg + bbv;
            float o1 = (xv[k].y - mu.y) * rs.y * gg + bbv;
            float o2 = (xv[k].z - mu.z) * rs.z * gg + bbv;
            float o3 = (xv[k].w - mu.w) * rs.w * gg + bbv;
            o0 *= sigm(o0); o1 *= sigm(o1); o2 *= sigm(o2); o3 *= sigm(o3);
            bstore(OFF_BA, c, o0, o1, o2, o3);
        }
    }
    __syncthreads();

    const unsigned char* wf = g_wfrag;
    const int c0 = wid * 16 + (lane >> 2);
    const int nb = (lane & 3) * 2;
    auto wptr = [&](int q) { return wf + (size_t)(q * 64 + wid) * 512 + (size_t)lane * 16; };

    auto kstore = [&](char* bk, int nt, float a0, float a1, float a2, float a3) {
        uint32_t a_off  = (uint32_t)((nt ^ (c0 & 7)) << 4) + (uint32_t)((lane & 3) * 4);
        uint32_t a_off8 = (uint32_t)((nt ^ ((c0 + 8) & 7)) << 4) + (uint32_t)((lane & 3) * 4);
        *reinterpret_cast<uint32_t*>(bk + c0 * 128 + a_off)        = pack_h(a0, a1);
        *reinterpret_cast<uint32_t*>(bk + (c0 + 8) * 128 + a_off8) = pack_h(a2, a3);
    };
    auto relu2 = [](float v) { return v > 0.f ? v * v : 0.f; };
    // relu^2 + store from f16-D accumulator pair
    auto kstoreh = [&](char* bk, int nt, uint32_t d0, uint32_t d1) {
        float2 v0 = unpack_h(d0), v1 = unpack_h(d1);
        kstore(bk, nt, relu2(v0.x), relu2(v0.y), relu2(v1.x), relu2(v1.y));
    };

    float acc[8][4];

    // ---- att = Wout @ y1s ; X += att
    zero8(acc);
    gemm16(acc, wptr(0), smb + OFF_BA, lane);
    #pragma unroll
    for (int nt = 0; nt < 8; nt++) {
        int n = nt * 8 + nb;
        float2* p0 = reinterpret_cast<float2*>(&X[XI(c0) + n]);
        float2* p1 = reinterpret_cast<float2*>(&X[XI(c0 + 8) + n]);
        float2 v0 = *p0, v1 = *p1;
        v0.x += acc[nt][0]; v0.y += acc[nt][1];
        v1.x += acc[nt][2]; v1.y += acc[nt][3];
        *p0 = v0; *p1 = v1;
    }
    __syncthreads();

    // ---- LN2: X -> y2 (BA)
    {
        float4 xv[8];
        float4 s1 = make_float4(0,0,0,0), s2 = make_float4(0,0,0,0);
        #pragma unroll
        for (int k = 0; k < 8; k++) {
            xv[k] = *reinterpret_cast<const float4*>(&X[XI(part * 8 + k) + lt0]);
            s1.x += xv[k].x; s1.y += xv[k].y; s1.z += xv[k].z; s1.w += xv[k].w;
            s2.x += xv[k].x*xv[k].x; s2.y += xv[k].y*xv[k].y;
            s2.z += xv[k].z*xv[k].z; s2.w += xv[k].w*xv[k].w;
        }
        s1 = red16(s1); s2 = red16(s2);
        float4 mu, rs;
        mu.x = s1.x*(1.f/C); mu.y = s1.y*(1.f/C); mu.z = s1.z*(1.f/C); mu.w = s1.w*(1.f/C);
        rs.x = rsqrtf(s2.x*(1.f/C) - mu.x*mu.x + 1e-5f);
        rs.y = rsqrtf(s2.y*(1.f/C) - mu.y*mu.y + 1e-5f);
        rs.z = rsqrtf(s2.z*(1.f/C) - mu.z*mu.z + 1e-5f);
        rs.w = rsqrtf(s2.w*(1.f/C) - mu.w*mu.w + 1e-5f);
        #pragma unroll
        for (int k = 0; k < 8; k++) {
            int c = part * 8 + k;
            float gg = __ldg(ln2_g + c), bbv = __ldg(ln2_b + c);
            bstore(OFF_BA, c,
                (xv[k].x - mu.x) * rs.x * gg + bbv,
                (xv[k].y - mu.y) * rs.y * gg + bbv,
                (xv[k].z - mu.z) * rs.z * gg + bbv,
                (xv[k].w - mu.w) * rs.w * gg + bbv);
        }
    }
    __syncthreads();

    // ---- wht = Wwhiten @ y2 -> BW (fp16, f32-D)
    zero8(acc);
    gemm16(acc, wptr(1), smb + OFF_BA, lane);
    #pragma unroll
    for (int nt = 0; nt < 8; nt++)
        kstore(sm + OFF_BW, nt, acc[nt][0], acc[nt][1], acc[nt][2], acc[nt][3]);
    __syncthreads();   // BW visible; all BA reads (whiten) complete

    // ---- fused f16-D: recep + key0, one BW pass. r -> regs, k0 -> BA
    uint32_t h0[8][2], h1[8][2];
    zero8h(h0); zero8h(h1);
    gemm16x2h(h0, h1, wptr(2), wptr(3), smb + OFF_BW, lane);
    uint32_t rpk[16];
    #pragma unroll
    for (int nt = 0; nt < 8; nt++) {
        float2 r0 = unpack_h(h0[nt][0]), r1 = unpack_h(h0[nt][1]);
        rpk[2*nt]   = pack_h(sigm(r0.x), sigm(r0.y));
        rpk[2*nt+1] = pack_h(sigm(r1.x), sigm(r1.y));
    }
    #pragma unroll
    for (int nt = 0; nt < 8; nt++)
        kstoreh(sm + OFF_BA, nt, h1[nt][0], h1[nt][1]);

    // ---- fused f16-D: key1 + key2, one BW pass -> BK, K2
    zero8h(h0); zero8h(h1);
    gemm16x2h(h0, h1, wptr(4), wptr(5), smb + OFF_BW, lane);
    #pragma unroll
    for (int nt = 0; nt < 8; nt++)
        kstoreh(sm + OFF_BK, nt, h0[nt][0], h0[nt][1]);
    #pragma unroll
    for (int nt = 0; nt < 8; nt++)
        kstoreh(sm + OFF_K2, nt, h1[nt][0], h1[nt][1]);

    // ---- f16-D: key3, last BW read; then k3 overwrites BW
    zero8h(h0);
    gemm16h(h0, wptr(6), smb + OFF_BW, lane);
    __syncthreads();   // all BW reads retired; k0/k1/k2 stores visible
    #pragma unroll
    for (int nt = 0; nt < 8; nt++)
        kstoreh(sm + OFF_BW, nt, h0[nt][0], h0[nt][1]);

    // ---- values (f32-D): v0..v2 back-to-back, sync, v3
    float accKV[8][4];
    zero8(accKV);
    gemm16(accKV, wptr(7), smb + OFF_BA, lane);
    gemm16(accKV, wptr(8), smb + OFF_BK, lane);
    gemm16(accKV, wptr(9), smb + OFF_K2, lane);
    __syncthreads();   // k3 stores to BW visible
    gemm16(accKV, wptr(10), smb + OFF_BW, lane);

    // ---- out = 2 * (X + r * kv)   (r from registers)
    #pragma unroll
    for (int nt = 0; nt < 8; nt++) {
        int n = nt * 8 + nb;
        float2 r0 = unpack_h(rpk[2*nt]);
        float2 r1 = unpack_h(rpk[2*nt+1]);
        float2 x0 = *reinterpret_cast<float2*>(&X[XI(c0) + n]);
        float2 x1 = *reinterpret_cast<float2*>(&X[XI(c0 + 8) + n]);
        float2 o0, o1;
        o0.x = 2.0f * (x0.x + r0.x * accKV[nt][0]);
        o0.y = 2.0f * (x0.y + r0.y * accKV[nt][1]);
        o1.x = 2.0f * (x1.x + r1.x * accKV[nt][2]);
        o1.y = 2.0f * (x1.y + r1.y * accKV[nt][3]);
        *reinterpret_cast<float2*>(&ob[c0 * HW + n]) = o0;
        *reinterpret_cast<float2*>(&ob[(c0 + 8) * HW + n]) = o1;
    }
}

extern "C" void kernel_launch(void* const* d_in, const int* in_sizes, int n_in,
                              void* d_out, int out_size)
{
    const float* x       = (const float*)d_in[0];
    const float* ln0_g   = (const float*)d_in[1];
    const float* ln0_b   = (const float*)d_in[2];
    const float* ln1_g   = (const float*)d_in[3];
    const float* ln1_b   = (const float*)d_in[4];
    const float* ln2_g   = (const float*)d_in[5];
    const float* ln2_b   = (const float*)d_in[6];
    const float* Wout    = (const float*)d_in[7];
    const float* Wwhiten = (const float*)d_in[8];
    const float* Wkey    = (const float*)d_in[9];
    const float* Wrecep  = (const float*)d_in[10];
    const float* Wvalue  = (const float*)d_in[11];
    float* out = (float*)d_out;

    prep_kernel<<<88, NTH>>>(Wout, Wwhiten, Wkey, Wrecep, Wvalue);

    cudaFuncSetAttribute(rwkv_mma_kernel,
                         cudaFuncAttributeMaxDynamicSharedMemorySize, SMEM_TOT);
    rwkv_mma_kernel<<<1024, NTH, SMEM_TOT>>>(
        x, ln0_g, ln0_b, ln1_g, ln1_b, ln2_g, ln2_b, out);
}